// round 8
// baseline (speedup 1.0000x reference)
#include <cuda_runtime.h>
#include <cuda_bf16.h>
#include <cuda_fp16.h>
#include <math.h>

#define SEQ 4096
#define DM  1024
#define NH  16
#define DK  64

// Scratch (allocation-guard-safe device globals)
__device__ __half g_Qs[SEQ * DM];    // Q fp16, pre-scaled by 1/sqrt(dk)*log2(e)
__device__ __half g_K[SEQ * DM];     // K fp16
__device__ __half g_V[SEQ * DM];     // V fp16
__device__ float  g_attn[SEQ * DM];

// ---------------------------------------------------------------------------
// PTX helpers
// ---------------------------------------------------------------------------
__device__ __forceinline__ void mma_bf16(float* c, const unsigned* a,
                                         unsigned b0, unsigned b1) {
    asm volatile(
        "mma.sync.aligned.m16n8k16.row.col.f32.bf16.bf16.f32 "
        "{%0,%1,%2,%3}, {%4,%5,%6,%7}, {%8,%9}, {%0,%1,%2,%3};"
        : "+f"(c[0]), "+f"(c[1]), "+f"(c[2]), "+f"(c[3])
        : "r"(a[0]), "r"(a[1]), "r"(a[2]), "r"(a[3]), "r"(b0), "r"(b1));
}
__device__ __forceinline__ void mma_f16(float* c, const unsigned* a,
                                        unsigned b0, unsigned b1) {
    asm volatile(
        "mma.sync.aligned.m16n8k16.row.col.f32.f16.f16.f32 "
        "{%0,%1,%2,%3}, {%4,%5,%6,%7}, {%8,%9}, {%0,%1,%2,%3};"
        : "+f"(c[0]), "+f"(c[1]), "+f"(c[2]), "+f"(c[3])
        : "r"(a[0]), "r"(a[1]), "r"(a[2]), "r"(a[3]), "r"(b0), "r"(b1));
}
__device__ __forceinline__ void ldsm_x4(unsigned& r0, unsigned& r1,
                                        unsigned& r2, unsigned& r3, unsigned a) {
    asm volatile("ldmatrix.sync.aligned.m8n8.x4.shared.b16 {%0,%1,%2,%3}, [%4];"
                 : "=r"(r0), "=r"(r1), "=r"(r2), "=r"(r3) : "r"(a));
}
__device__ __forceinline__ void ldsm_x4_t(unsigned& r0, unsigned& r1,
                                          unsigned& r2, unsigned& r3, unsigned a) {
    asm volatile("ldmatrix.sync.aligned.m8n8.x4.trans.shared.b16 {%0,%1,%2,%3}, [%4];"
                 : "=r"(r0), "=r"(r1), "=r"(r2), "=r"(r3) : "r"(a));
}
__device__ __forceinline__ unsigned pack_f16(float lo, float hi) {
    unsigned r; asm("cvt.rn.f16x2.f32 %0, %1, %2;" : "=r"(r) : "f"(hi), "f"(lo));
    return r;
}
__device__ __forceinline__ float ex2(float x) {
    float r; asm("ex2.approx.ftz.f32 %0, %1;" : "=f"(r) : "f"(x)); return r;
}
__device__ __forceinline__ void bsplit(float2 f, unsigned& hi, unsigned& lo) {
    __nv_bfloat162 h = __float22bfloat162_rn(f);
    float2 hf = __bfloat1622float2(h);
    __nv_bfloat162 l = __float22bfloat162_rn(make_float2(f.x - hf.x, f.y - hf.y));
    hi = *(unsigned*)&h;
    lo = *(unsigned*)&l;
}
__device__ __forceinline__ void cp16(unsigned dst, const void* src) {
    asm volatile("cp.async.cg.shared.global [%0], [%1], 16;"
                 :: "r"(dst), "l"(src));
}

// ---------------------------------------------------------------------------
// bf16-split tensor-core GEMM: C = A @ B^T + bias, then optional scale.
// OMODE 0: fp32 C.  OMODE 2: fp16 C (value = (acc+bias)*oscale).
// ---------------------------------------------------------------------------
#define GP 40
#define GBUF (128 * GP)

template <int OMODE>
__global__ __launch_bounds__(256) void gemm_bf16x3(
    const float* __restrict__ A, const float* __restrict__ B,
    const float* __restrict__ bias, void* __restrict__ C0,
    float oscale, int M, int N, int Kd)
{
    extern __shared__ float smem[];
    float* sA = smem;
    float* sB = smem + 2 * GBUF;

    const int tid  = threadIdx.x;
    const int lane = tid & 31;
    const int warp = tid >> 5;
    const int wy = warp & 3;
    const int wx = warp >> 2;
    const int bm0 = blockIdx.y * 128;
    const int bn0 = blockIdx.x * 128;

    const int lr = tid >> 3;
    const int lc = (tid & 7) << 2;

    float acc[2][8][4];
    #pragma unroll
    for (int mf = 0; mf < 2; mf++)
        #pragma unroll
        for (int nf = 0; nf < 8; nf++)
            #pragma unroll
            for (int i = 0; i < 4; i++) acc[mf][nf][i] = 0.0f;

    #pragma unroll
    for (int p = 0; p < 4; p++) {
        int row = lr + 32 * p;
        *(float4*)&sA[row * GP + lc] = *(const float4*)(A + (size_t)(bm0 + row) * Kd + lc);
        *(float4*)&sB[row * GP + lc] = *(const float4*)(B + (size_t)(bn0 + row) * Kd + lc);
    }
    __syncthreads();

    const int NT = Kd >> 5;
    float4 ra[4], rb[4];
    const int p2 = (lane & 3) << 1;
    const int arow = wy * 32 + (lane >> 2);
    const int brow = wx * 64 + (lane >> 2);

    for (int kt = 0; kt < NT; kt++) {
        const int buf = kt & 1;
        if (kt + 1 < NT) {
            #pragma unroll
            for (int p = 0; p < 4; p++) {
                int row = lr + 32 * p;
                ra[p] = *(const float4*)(A + (size_t)(bm0 + row) * Kd + (kt + 1) * 32 + lc);
                rb[p] = *(const float4*)(B + (size_t)(bn0 + row) * Kd + (kt + 1) * 32 + lc);
            }
        }
        const float* cA = sA + buf * GBUF;
        const float* cB = sB + buf * GBUF;

        #pragma unroll
        for (int ks = 0; ks < 2; ks++) {
            const int ko = ks * 16;
            unsigned ah[2][4], al[2][4];
            #pragma unroll
            for (int mf = 0; mf < 2; mf++) {
                int r = arow + mf * 16;
                bsplit(*(const float2*)&cA[r * GP + ko + p2],           ah[mf][0], al[mf][0]);
                bsplit(*(const float2*)&cA[(r + 8) * GP + ko + p2],     ah[mf][1], al[mf][1]);
                bsplit(*(const float2*)&cA[r * GP + ko + 8 + p2],       ah[mf][2], al[mf][2]);
                bsplit(*(const float2*)&cA[(r + 8) * GP + ko + 8 + p2], ah[mf][3], al[mf][3]);
            }
            #pragma unroll
            for (int nf = 0; nf < 8; nf++) {
                int r = brow + nf * 8;
                unsigned bh0, bl0, bh1, bl1;
                bsplit(*(const float2*)&cB[r * GP + ko + p2],     bh0, bl0);
                bsplit(*(const float2*)&cB[r * GP + ko + 8 + p2], bh1, bl1);
                #pragma unroll
                for (int mf = 0; mf < 2; mf++) {
                    mma_bf16(acc[mf][nf], ah[mf], bh0, bh1);
                    mma_bf16(acc[mf][nf], al[mf], bh0, bh1);
                    mma_bf16(acc[mf][nf], ah[mf], bl0, bl1);
                }
            }
        }

        if (kt + 1 < NT) {
            float* nA = sA + (1 - buf) * GBUF;
            float* nB = sB + (1 - buf) * GBUF;
            #pragma unroll
            for (int p = 0; p < 4; p++) {
                int row = lr + 32 * p;
                *(float4*)&nA[row * GP + lc] = ra[p];
                *(float4*)&nB[row * GP + lc] = rb[p];
            }
        }
        __syncthreads();
    }

    #pragma unroll
    for (int mf = 0; mf < 2; mf++) {
        #pragma unroll
        for (int nf = 0; nf < 8; nf++) {
            int r  = bm0 + wy * 32 + mf * 16 + (lane >> 2);
            int cc = bn0 + wx * 64 + nf * 8 + 2 * (lane & 3);
            float bv0 = bias[cc], bv1 = bias[cc + 1];
            float2 v0 = make_float2(acc[mf][nf][0] + bv0, acc[mf][nf][1] + bv1);
            float2 v1 = make_float2(acc[mf][nf][2] + bv0, acc[mf][nf][3] + bv1);
            if (OMODE == 0) {
                float* C = (float*)C0;
                *(float2*)(C + (size_t)r * N + cc)       = v0;
                *(float2*)(C + (size_t)(r + 8) * N + cc) = v1;
            } else {
                __half* C = (__half*)C0;
                *(unsigned*)(C + (size_t)r * N + cc) =
                    pack_f16(v0.x * oscale, v0.y * oscale);
                *(unsigned*)(C + (size_t)(r + 8) * N + cc) =
                    pack_f16(v1.x * oscale, v1.y * oscale);
            }
        }
    }
}

// ---------------------------------------------------------------------------
// Tensor-core flash attention, v4: all-fp16 operands, cp.async 3-stage.
// 256 threads (8 warps), 128 queries/block, 64-key tiles, 2 CTAs/SM.
// QK^T: single-pass fp16 mma. PV: fp16 mma. B-frags via ldmatrix.x4.
// ---------------------------------------------------------------------------
#define KST 72                        // half-element stride (144 B rows)
#define TILE_B (64 * KST * 2)         // 9216 B per plane
#define STAGE_B (2 * TILE_B)          // K + V = 18432 B
#define NSTAGE 3
#define QROWB (KST * 2)               // Q staging row stride bytes (144)

__global__ __launch_bounds__(256, 2) void fattn_kernel(
    const __half* __restrict__ Q, const __half* __restrict__ K,
    const __half* __restrict__ V, float* __restrict__ O)
{
    extern __shared__ char dsm[];     // NSTAGE * STAGE_B = 55296 B

    const int tid  = threadIdx.x;
    const int lane = tid & 31;
    const int warp = tid >> 5;
    const int h    = blockIdx.y;
    const int q0   = blockIdx.x * 128;
    const int hoff = h * DK;

    const unsigned smem_base = (unsigned)__cvta_generic_to_shared(dsm);

    // ---- stage Q tile (fp16, pre-scaled) via cp.async, lift A-frags
    {
        int qr = tid >> 1;                     // 0..127
        int qc = (tid & 1) * 64;               // byte chunk within 128 B row
        const char* src = (const char*)(Q + (size_t)(q0 + qr) * DM + hoff) + qc;
        unsigned dst = smem_base + qr * QROWB + qc;
        cp16(dst, src);  cp16(dst + 16, src + 16);
        cp16(dst + 32, src + 32);  cp16(dst + 48, src + 48);
    }
    asm volatile("cp.async.commit_group;");
    asm volatile("cp.async.wait_group 0;");
    __syncthreads();

    unsigned qf[4][4];
    {
        const unsigned qrow = warp * 16 + (lane & 15);
        #pragma unroll
        for (int s4 = 0; s4 < 4; s4++) {
            unsigned addr = smem_base + qrow * QROWB + (s4 * 16 + 8 * (lane >> 4)) * 2;
            ldsm_x4(qf[s4][0], qf[s4][1], qf[s4][2], qf[s4][3], addr);
        }
    }
    __syncthreads();

    // ---- cp.async tile loader: thread -> row (tid>>2), 32B chunk (tid&3)
    const int lrow = tid >> 2;
    const int lcb  = (tid & 3) * 32;
    const char* srcK = (const char*)(K + (size_t)lrow * DM + hoff) + lcb;
    const char* srcV = (const char*)(V + (size_t)lrow * DM + hoff) + lcb;
    const unsigned drow = smem_base + lrow * (KST * 2) + lcb;

    auto load_stage = [&](int t, int sbuf) {
        size_t goff = (size_t)t * 64 * DM * 2;
        unsigned d = drow + sbuf * STAGE_B;
        cp16(d, srcK + goff);           cp16(d + 16, srcK + goff + 16);
        cp16(d + TILE_B, srcV + goff);  cp16(d + TILE_B + 16, srcV + goff + 16);
    };

    const int NTILE = SEQ / 64;
    load_stage(0, 0);
    asm volatile("cp.async.commit_group;");
    load_stage(1, 1);
    asm volatile("cp.async.commit_group;");

    const unsigned k_off = ((8 * ((lane >> 4) & 1) + (lane & 7)) * KST
                            + 8 * ((lane >> 3) & 1)) * 2;
    const unsigned v_off = ((8 * ((lane >> 3) & 1) + (lane & 7)) * KST
                            + 8 * (lane >> 4)) * 2;

    float o[8][4];
    #pragma unroll
    for (int df = 0; df < 8; df++)
        #pragma unroll
        for (int i = 0; i < 4; i++) o[df][i] = 0.0f;
    float m0 = -1e30f, m1 = -1e30f, l0s = 0.0f, l1s = 0.0f;

    for (int t = 0; t < NTILE; t++) {
        const int buf = t % NSTAGE;
        const unsigned stage = smem_base + buf * STAGE_B;

        asm volatile("cp.async.wait_group 1;");
        __syncthreads();

        if (t + 2 < NTILE) load_stage(t + 2, (t + 2) % NSTAGE);
        asm volatile("cp.async.commit_group;");

        // ---- S = Q*K^T (single-pass fp16)
        float s[8][4];
        #pragma unroll
        for (int nf = 0; nf < 8; nf++)
            #pragma unroll
            for (int i = 0; i < 4; i++) s[nf][i] = 0.0f;

        #pragma unroll
        for (int s4 = 0; s4 < 4; s4++) {
            const int d0 = 16 * s4;
            #pragma unroll
            for (int nfp = 0; nfp < 4; nfp++) {
                const unsigned off = (unsigned)((16 * nfp) * KST + d0) * 2 + k_off;
                unsigned h0, h1, h2, h3;
                ldsm_x4(h0, h1, h2, h3, stage + off);
                mma_f16(s[2 * nfp],     qf[s4], h0, h1);
                mma_f16(s[2 * nfp + 1], qf[s4], h2, h3);
            }
        }

        // ---- online softmax (rows: A = lane/4, B = lane/4 + 8)
        float mx0 = -1e30f, mx1 = -1e30f;
        #pragma unroll
        for (int nf = 0; nf < 8; nf++) {
            mx0 = fmaxf(mx0, fmaxf(s[nf][0], s[nf][1]));
            mx1 = fmaxf(mx1, fmaxf(s[nf][2], s[nf][3]));
        }
        mx0 = fmaxf(mx0, __shfl_xor_sync(0xffffffffu, mx0, 1));
        mx0 = fmaxf(mx0, __shfl_xor_sync(0xffffffffu, mx0, 2));
        mx1 = fmaxf(mx1, __shfl_xor_sync(0xffffffffu, mx1, 1));
        mx1 = fmaxf(mx1, __shfl_xor_sync(0xffffffffu, mx1, 2));

        float nm0 = fmaxf(m0, mx0), nm1 = fmaxf(m1, mx1);
        float a0 = ex2(m0 - nm0), a1 = ex2(m1 - nm1);
        m0 = nm0; m1 = nm1;

        unsigned pp[8][2];
        float ps0 = 0.0f, ps1 = 0.0f;
        #pragma unroll
        for (int nf = 0; nf < 8; nf++) {
            float p0 = ex2(s[nf][0] - nm0);
            float p1 = ex2(s[nf][1] - nm0);
            float p2 = ex2(s[nf][2] - nm1);
            float p3 = ex2(s[nf][3] - nm1);
            ps0 += p0 + p1;
            ps1 += p2 + p3;
            pp[nf][0] = pack_f16(p0, p1);
            pp[nf][1] = pack_f16(p2, p3);
        }
        l0s = l0s * a0 + ps0;
        l1s = l1s * a1 + ps1;

        #pragma unroll
        for (int df = 0; df < 8; df++) {
            o[df][0] *= a0; o[df][1] *= a0;
            o[df][2] *= a1; o[df][3] *= a1;
        }

        // ---- O += P*V (fp16 mma; V B-frags via ldmatrix.trans)
        #pragma unroll
        for (int kf2 = 0; kf2 < 4; kf2++) {
            unsigned af[4];
            af[0] = pp[2 * kf2][0];
            af[1] = pp[2 * kf2][1];
            af[2] = pp[2 * kf2 + 1][0];
            af[3] = pp[2 * kf2 + 1][1];
            #pragma unroll
            for (int dfp = 0; dfp < 4; dfp++) {
                const unsigned off = (unsigned)((16 * kf2) * KST + 16 * dfp) * 2 + v_off;
                unsigned b0, b1, b2, b3;
                ldsm_x4_t(b0, b1, b2, b3, stage + TILE_B + off);
                mma_f16(o[2 * dfp],     af, b0, b1);
                mma_f16(o[2 * dfp + 1], af, b2, b3);
            }
        }
    }

    // ---- finalize
    l0s += __shfl_xor_sync(0xffffffffu, l0s, 1);
    l0s += __shfl_xor_sync(0xffffffffu, l0s, 2);
    l1s += __shfl_xor_sync(0xffffffffu, l1s, 1);
    l1s += __shfl_xor_sync(0xffffffffu, l1s, 2);
    float i0 = 1.0f / l0s, i1 = 1.0f / l1s;

    const int grow = q0 + warp * 16 + (lane >> 2);
    #pragma unroll
    for (int df = 0; df < 8; df++) {
        int col = hoff + df * 8 + 2 * (lane & 3);
        *(float2*)(O + (size_t)grow * DM + col) =
            make_float2(o[df][0] * i0, o[df][1] * i0);
        *(float2*)(O + (size_t)(grow + 8) * DM + col) =
            make_float2(o[df][2] * i1, o[df][3] * i1);
    }
}

// ---------------------------------------------------------------------------
extern "C" void kernel_launch(void* const* d_in, const int* in_sizes, int n_in,
                              void* d_out, int out_size)
{
    const float* query = (const float*)d_in[0];
    const float* key   = (const float*)d_in[1];
    const float* value = (const float*)d_in[2];
    const float* W_q   = (const float*)d_in[3];
    const float* b_q   = (const float*)d_in[4];
    const float* W_k   = (const float*)d_in[5];
    const float* b_k   = (const float*)d_in[6];
    const float* W_v   = (const float*)d_in[7];
    const float* b_v   = (const float*)d_in[8];
    const float* W_o   = (const float*)d_in[9];
    const float* b_o   = (const float*)d_in[10];
    float* out = (float*)d_out;

    __half *Qp, *Kp, *Vp;
    float *Ap;
    cudaGetSymbolAddress((void**)&Qp, g_Qs);
    cudaGetSymbolAddress((void**)&Kp, g_K);
    cudaGetSymbolAddress((void**)&Vp, g_V);
    cudaGetSymbolAddress((void**)&Ap, g_attn);

    const float SC = 0.125f * 1.4426950408889634f;   // 1/sqrt(64) * log2(e)

    const int gsmem = 2 * 2 * GBUF * (int)sizeof(float);   // 81920 B
    const int fsmem = NSTAGE * STAGE_B;                     // 55296 B
    static int attr_set = 0;
    if (!attr_set) {
        cudaFuncSetAttribute(gemm_bf16x3<0>, cudaFuncAttributeMaxDynamicSharedMemorySize, gsmem);
        cudaFuncSetAttribute(gemm_bf16x3<2>, cudaFuncAttributeMaxDynamicSharedMemorySize, gsmem);
        cudaFuncSetAttribute(fattn_kernel, cudaFuncAttributeMaxDynamicSharedMemorySize, fsmem);
        attr_set = 1;
    }

    dim3 ggrd(DM / 128, SEQ / 128);
    gemm_bf16x3<2><<<ggrd, 256, gsmem>>>(query, W_q, b_q, Qp, SC,   SEQ, DM, DM);
    gemm_bf16x3<2><<<ggrd, 256, gsmem>>>(key,   W_k, b_k, Kp, 1.0f, SEQ, DM, DM);
    gemm_bf16x3<2><<<ggrd, 256, gsmem>>>(value, W_v, b_v, Vp, 1.0f, SEQ, DM, DM);

    dim3 agrd(SEQ / 128, NH);
    fattn_kernel<<<agrd, 256, fsmem>>>(Qp, Kp, Vp, Ap);

    gemm_bf16x3<0><<<ggrd, 256, gsmem>>>(Ap, W_o, b_o, out, 1.0f, SEQ, DM, DM);
}

// round 9
// speedup vs baseline: 1.7170x; 1.7170x over previous
#include <cuda_runtime.h>
#include <cuda_bf16.h>
#include <cuda_fp16.h>
#include <math.h>

#define SEQ 4096
#define DM  1024
#define NH  16
#define DK  64

// Scratch (allocation-guard-safe device globals)
__device__ __half g_Qs[SEQ * DM];    // Q fp16, pre-scaled by 1/sqrt(dk)*log2(e)
__device__ __half g_K[SEQ * DM];     // K fp16
__device__ __half g_V[SEQ * DM];     // V fp16
__device__ float  g_attn[SEQ * DM];

// ---------------------------------------------------------------------------
// PTX helpers
// ---------------------------------------------------------------------------
__device__ __forceinline__ void mma_bf16(float* c, const unsigned* a,
                                         unsigned b0, unsigned b1) {
    asm volatile(
        "mma.sync.aligned.m16n8k16.row.col.f32.bf16.bf16.f32 "
        "{%0,%1,%2,%3}, {%4,%5,%6,%7}, {%8,%9}, {%0,%1,%2,%3};"
        : "+f"(c[0]), "+f"(c[1]), "+f"(c[2]), "+f"(c[3])
        : "r"(a[0]), "r"(a[1]), "r"(a[2]), "r"(a[3]), "r"(b0), "r"(b1));
}
__device__ __forceinline__ void mma_f16(float* c, const unsigned* a,
                                        unsigned b0, unsigned b1) {
    asm volatile(
        "mma.sync.aligned.m16n8k16.row.col.f32.f16.f16.f32 "
        "{%0,%1,%2,%3}, {%4,%5,%6,%7}, {%8,%9}, {%0,%1,%2,%3};"
        : "+f"(c[0]), "+f"(c[1]), "+f"(c[2]), "+f"(c[3])
        : "r"(a[0]), "r"(a[1]), "r"(a[2]), "r"(a[3]), "r"(b0), "r"(b1));
}
__device__ __forceinline__ void ldsm_x4(unsigned& r0, unsigned& r1,
                                        unsigned& r2, unsigned& r3, unsigned a) {
    asm volatile("ldmatrix.sync.aligned.m8n8.x4.shared.b16 {%0,%1,%2,%3}, [%4];"
                 : "=r"(r0), "=r"(r1), "=r"(r2), "=r"(r3) : "r"(a));
}
__device__ __forceinline__ void ldsm_x4_t(unsigned& r0, unsigned& r1,
                                          unsigned& r2, unsigned& r3, unsigned a) {
    asm volatile("ldmatrix.sync.aligned.m8n8.x4.trans.shared.b16 {%0,%1,%2,%3}, [%4];"
                 : "=r"(r0), "=r"(r1), "=r"(r2), "=r"(r3) : "r"(a));
}
__device__ __forceinline__ unsigned pack_f16(float lo, float hi) {
    unsigned r; asm("cvt.rn.f16x2.f32 %0, %1, %2;" : "=r"(r) : "f"(hi), "f"(lo));
    return r;
}
__device__ __forceinline__ float ex2(float x) {
    float r; asm("ex2.approx.ftz.f32 %0, %1;" : "=f"(r) : "f"(x)); return r;
}
__device__ __forceinline__ void bsplit(float2 f, unsigned& hi, unsigned& lo) {
    __nv_bfloat162 h = __float22bfloat162_rn(f);
    float2 hf = __bfloat1622float2(h);
    __nv_bfloat162 l = __float22bfloat162_rn(make_float2(f.x - hf.x, f.y - hf.y));
    hi = *(unsigned*)&h;
    lo = *(unsigned*)&l;
}
__device__ __forceinline__ void cp16(unsigned dst, const void* src) {
    asm volatile("cp.async.cg.shared.global [%0], [%1], 16;"
                 :: "r"(dst), "l"(src));
}

// ---------------------------------------------------------------------------
// bf16-split tensor-core GEMM v2: C = A @ B^T + bias (then optional scale).
// hi/lo split happens ONCE at tile staging; smem holds bf16 planes
// (Ah/Al/Bh/Bl, stride 40 halves -> LDSM conflict-free); fragments via
// ldmatrix.x4. 3 MMAs per k16: Ah*Bh + Al*Bh + Ah*Bl.
// Block 256 thr (8 warps 4x2), tile 128x128x32, double-buffered.
// OMODE 0: fp32 C.  OMODE 2: fp16 C (value = (acc+bias)*oscale).
// ---------------------------------------------------------------------------
#define GP2 40                        // plane row stride in halves (80 B)
#define PLANE_B (128 * GP2 * 2)       // 10240 B per plane
#define GBUF_B (4 * PLANE_B)          // Ah,Al,Bh,Bl = 40960 B per buffer

template <int OMODE>
__global__ __launch_bounds__(256) void gemm_split(
    const float* __restrict__ A, const float* __restrict__ B,
    const float* __restrict__ bias, void* __restrict__ C0,
    float oscale, int M, int N, int Kd)
{
    extern __shared__ char dsm[];     // 2 * GBUF_B = 81920 B
    const unsigned sbase = (unsigned)__cvta_generic_to_shared(dsm);

    const int tid  = threadIdx.x;
    const int lane = tid & 31;
    const int warp = tid >> 5;
    const int wy = warp & 3;          // m: 4 warps of 32 rows
    const int wx = warp >> 2;         // n: 2 warps of 64 cols
    const int bm0 = blockIdx.y * 128;
    const int bn0 = blockIdx.x * 128;

    const int lr = tid >> 3;          // 0..31 (row within 32-row pass)
    const int lc = (tid & 7) << 2;    // 0..28 (k, float4-aligned)

    float acc[2][8][4];
    #pragma unroll
    for (int mf = 0; mf < 2; mf++)
        #pragma unroll
        for (int nf = 0; nf < 8; nf++)
            #pragma unroll
            for (int i = 0; i < 4; i++) acc[mf][nf][i] = 0.0f;

    float4 ra[4], rb[4];

    // split regs -> bf16 planes of buffer `buf`
    auto store_split = [&](int buf) {
        char* bb = dsm + buf * GBUF_B;
        #pragma unroll
        for (int p = 0; p < 4; p++) {
            int row = lr + 32 * p;
            int off = (row * GP2 + lc) * 2;      // byte offset in plane
            unsigned h0, l0, h1, l1;
            bsplit(make_float2(ra[p].x, ra[p].y), h0, l0);
            bsplit(make_float2(ra[p].z, ra[p].w), h1, l1);
            *(uint2*)(bb + off)               = make_uint2(h0, h1);  // Ah
            *(uint2*)(bb + PLANE_B + off)     = make_uint2(l0, l1);  // Al
            bsplit(make_float2(rb[p].x, rb[p].y), h0, l0);
            bsplit(make_float2(rb[p].z, rb[p].w), h1, l1);
            *(uint2*)(bb + 2 * PLANE_B + off) = make_uint2(h0, h1);  // Bh
            *(uint2*)(bb + 3 * PLANE_B + off) = make_uint2(l0, l1);  // Bl
        }
    };

    // prologue: tile 0
    #pragma unroll
    for (int p = 0; p < 4; p++) {
        int row = lr + 32 * p;
        ra[p] = *(const float4*)(A + (size_t)(bm0 + row) * Kd + lc);
        rb[p] = *(const float4*)(B + (size_t)(bn0 + row) * Kd + lc);
    }
    store_split(0);
    __syncthreads();

    // per-lane ldmatrix address components (halves)
    const int a_row = (lane & 15);
    const int a_chk = 8 * (lane >> 4);
    const int b_row = 8 * ((lane >> 4) & 1) + (lane & 7);
    const int b_chk = 8 * ((lane >> 3) & 1);

    const int NT = Kd >> 5;
    for (int kt = 0; kt < NT; kt++) {
        const int buf = kt & 1;
        const unsigned bb = sbase + buf * GBUF_B;

        if (kt + 1 < NT) {
            #pragma unroll
            for (int p = 0; p < 4; p++) {
                int row = lr + 32 * p;
                ra[p] = *(const float4*)(A + (size_t)(bm0 + row) * Kd + (kt + 1) * 32 + lc);
                rb[p] = *(const float4*)(B + (size_t)(bn0 + row) * Kd + (kt + 1) * 32 + lc);
            }
        }

        #pragma unroll
        for (int ks = 0; ks < 2; ks++) {
            const int ko = ks * 16;
            unsigned ah[2][4], al[2][4];
            #pragma unroll
            for (int mf = 0; mf < 2; mf++) {
                unsigned addr = bb +
                    (unsigned)(((wy * 32 + mf * 16 + a_row) * GP2 + ko + a_chk) * 2);
                ldsm_x4(ah[mf][0], ah[mf][1], ah[mf][2], ah[mf][3], addr);
                ldsm_x4(al[mf][0], al[mf][1], al[mf][2], al[mf][3], addr + PLANE_B);
            }
            #pragma unroll
            for (int nfp = 0; nfp < 4; nfp++) {
                unsigned baddr = bb + 2 * PLANE_B +
                    (unsigned)(((wx * 64 + 16 * nfp + b_row) * GP2 + ko + b_chk) * 2);
                unsigned bh0, bh1, bh2, bh3, bl0, bl1, bl2, bl3;
                ldsm_x4(bh0, bh1, bh2, bh3, baddr);
                ldsm_x4(bl0, bl1, bl2, bl3, baddr + PLANE_B);
                #pragma unroll
                for (int mf = 0; mf < 2; mf++) {
                    mma_bf16(acc[mf][2 * nfp],     ah[mf], bh0, bh1);
                    mma_bf16(acc[mf][2 * nfp],     al[mf], bh0, bh1);
                    mma_bf16(acc[mf][2 * nfp],     ah[mf], bl0, bl1);
                    mma_bf16(acc[mf][2 * nfp + 1], ah[mf], bh2, bh3);
                    mma_bf16(acc[mf][2 * nfp + 1], al[mf], bh2, bh3);
                    mma_bf16(acc[mf][2 * nfp + 1], ah[mf], bl2, bl3);
                }
            }
        }

        if (kt + 1 < NT) {
            __syncthreads();          // all warps done reading buf^1 from prev iter
            store_split(1 - buf);
        }
        __syncthreads();
    }

    // epilogue with bias
    #pragma unroll
    for (int mf = 0; mf < 2; mf++) {
        #pragma unroll
        for (int nf = 0; nf < 8; nf++) {
            int r  = bm0 + wy * 32 + mf * 16 + (lane >> 2);
            int cc = bn0 + wx * 64 + nf * 8 + 2 * (lane & 3);
            float bv0 = bias[cc], bv1 = bias[cc + 1];
            float2 v0 = make_float2(acc[mf][nf][0] + bv0, acc[mf][nf][1] + bv1);
            float2 v1 = make_float2(acc[mf][nf][2] + bv0, acc[mf][nf][3] + bv1);
            if (OMODE == 0) {
                float* C = (float*)C0;
                *(float2*)(C + (size_t)r * N + cc)       = v0;
                *(float2*)(C + (size_t)(r + 8) * N + cc) = v1;
            } else {
                __half* C = (__half*)C0;
                *(unsigned*)(C + (size_t)r * N + cc) =
                    pack_f16(v0.x * oscale, v0.y * oscale);
                *(unsigned*)(C + (size_t)(r + 8) * N + cc) =
                    pack_f16(v1.x * oscale, v1.y * oscale);
            }
        }
    }
}

// ---------------------------------------------------------------------------
// Tensor-core flash attention, v4 (unchanged from round 8 — validated).
// 256 threads (8 warps), 128 queries/block, 64-key tiles, cp.async 3-stage.
// ---------------------------------------------------------------------------
#define KST 72
#define TILE_B (64 * KST * 2)
#define STAGE_B (2 * TILE_B)
#define NSTAGE 3
#define QROWB (KST * 2)

__global__ __launch_bounds__(256, 2) void fattn_kernel(
    const __half* __restrict__ Q, const __half* __restrict__ K,
    const __half* __restrict__ V, float* __restrict__ O)
{
    extern __shared__ char dsm[];

    const int tid  = threadIdx.x;
    const int lane = tid & 31;
    const int warp = tid >> 5;
    const int h    = blockIdx.y;
    const int q0   = blockIdx.x * 128;
    const int hoff = h * DK;

    const unsigned smem_base = (unsigned)__cvta_generic_to_shared(dsm);

    {
        int qr = tid >> 1;
        int qc = (tid & 1) * 64;
        const char* src = (const char*)(Q + (size_t)(q0 + qr) * DM + hoff) + qc;
        unsigned dst = smem_base + qr * QROWB + qc;
        cp16(dst, src);  cp16(dst + 16, src + 16);
        cp16(dst + 32, src + 32);  cp16(dst + 48, src + 48);
    }
    asm volatile("cp.async.commit_group;");
    asm volatile("cp.async.wait_group 0;");
    __syncthreads();

    unsigned qf[4][4];
    {
        const unsigned qrow = warp * 16 + (lane & 15);
        #pragma unroll
        for (int s4 = 0; s4 < 4; s4++) {
            unsigned addr = smem_base + qrow * QROWB + (s4 * 16 + 8 * (lane >> 4)) * 2;
            ldsm_x4(qf[s4][0], qf[s4][1], qf[s4][2], qf[s4][3], addr);
        }
    }
    __syncthreads();

    const int lrow = tid >> 2;
    const int lcb  = (tid & 3) * 32;
    const char* srcK = (const char*)(K + (size_t)lrow * DM + hoff) + lcb;
    const char* srcV = (const char*)(V + (size_t)lrow * DM + hoff) + lcb;
    const unsigned drow = smem_base + lrow * (KST * 2) + lcb;

    auto load_stage = [&](int t, int sbuf) {
        size_t goff = (size_t)t * 64 * DM * 2;
        unsigned d = drow + sbuf * STAGE_B;
        cp16(d, srcK + goff);           cp16(d + 16, srcK + goff + 16);
        cp16(d + TILE_B, srcV + goff);  cp16(d + TILE_B + 16, srcV + goff + 16);
    };

    const int NTILE = SEQ / 64;
    load_stage(0, 0);
    asm volatile("cp.async.commit_group;");
    load_stage(1, 1);
    asm volatile("cp.async.commit_group;");

    const unsigned k_off = ((8 * ((lane >> 4) & 1) + (lane & 7)) * KST
                            + 8 * ((lane >> 3) & 1)) * 2;
    const unsigned v_off = ((8 * ((lane >> 3) & 1) + (lane & 7)) * KST
                            + 8 * (lane >> 4)) * 2;

    float o[8][4];
    #pragma unroll
    for (int df = 0; df < 8; df++)
        #pragma unroll
        for (int i = 0; i < 4; i++) o[df][i] = 0.0f;
    float m0 = -1e30f, m1 = -1e30f, l0s = 0.0f, l1s = 0.0f;

    for (int t = 0; t < NTILE; t++) {
        const int buf = t % NSTAGE;
        const unsigned stage = smem_base + buf * STAGE_B;

        asm volatile("cp.async.wait_group 1;");
        __syncthreads();

        if (t + 2 < NTILE) load_stage(t + 2, (t + 2) % NSTAGE);
        asm volatile("cp.async.commit_group;");

        float s[8][4];
        #pragma unroll
        for (int nf = 0; nf < 8; nf++)
            #pragma unroll
            for (int i = 0; i < 4; i++) s[nf][i] = 0.0f;

        #pragma unroll
        for (int s4 = 0; s4 < 4; s4++) {
            const int d0 = 16 * s4;
            #pragma unroll
            for (int nfp = 0; nfp < 4; nfp++) {
                const unsigned off = (unsigned)((16 * nfp) * KST + d0) * 2 + k_off;
                unsigned h0, h1, h2, h3;
                ldsm_x4(h0, h1, h2, h3, stage + off);
                mma_f16(s[2 * nfp],     qf[s4], h0, h1);
                mma_f16(s[2 * nfp + 1], qf[s4], h2, h3);
            }
        }

        float mx0 = -1e30f, mx1 = -1e30f;
        #pragma unroll
        for (int nf = 0; nf < 8; nf++) {
            mx0 = fmaxf(mx0, fmaxf(s[nf][0], s[nf][1]));
            mx1 = fmaxf(mx1, fmaxf(s[nf][2], s[nf][3]));
        }
        mx0 = fmaxf(mx0, __shfl_xor_sync(0xffffffffu, mx0, 1));
        mx0 = fmaxf(mx0, __shfl_xor_sync(0xffffffffu, mx0, 2));
        mx1 = fmaxf(mx1, __shfl_xor_sync(0xffffffffu, mx1, 1));
        mx1 = fmaxf(mx1, __shfl_xor_sync(0xffffffffu, mx1, 2));

        float nm0 = fmaxf(m0, mx0), nm1 = fmaxf(m1, mx1);
        float a0 = ex2(m0 - nm0), a1 = ex2(m1 - nm1);
        m0 = nm0; m1 = nm1;

        unsigned pp[8][2];
        float ps0 = 0.0f, ps1 = 0.0f;
        #pragma unroll
        for (int nf = 0; nf < 8; nf++) {
            float p0 = ex2(s[nf][0] - nm0);
            float p1 = ex2(s[nf][1] - nm0);
            float p2 = ex2(s[nf][2] - nm1);
            float p3 = ex2(s[nf][3] - nm1);
            ps0 += p0 + p1;
            ps1 += p2 + p3;
            pp[nf][0] = pack_f16(p0, p1);
            pp[nf][1] = pack_f16(p2, p3);
        }
        l0s = l0s * a0 + ps0;
        l1s = l1s * a1 + ps1;

        #pragma unroll
        for (int df = 0; df < 8; df++) {
            o[df][0] *= a0; o[df][1] *= a0;
            o[df][2] *= a1; o[df][3] *= a1;
        }

        #pragma unroll
        for (int kf2 = 0; kf2 < 4; kf2++) {
            unsigned af[4];
            af[0] = pp[2 * kf2][0];
            af[1] = pp[2 * kf2][1];
            af[2] = pp[2 * kf2 + 1][0];
            af[3] = pp[2 * kf2 + 1][1];
            #pragma unroll
            for (int dfp = 0; dfp < 4; dfp++) {
                const unsigned off = (unsigned)((16 * kf2) * KST + 16 * dfp) * 2 + v_off;
                unsigned b0, b1, b2, b3;
                ldsm_x4_t(b0, b1, b2, b3, stage + TILE_B + off);
                mma_f16(o[2 * dfp],     af, b0, b1);
                mma_f16(o[2 * dfp + 1], af, b2, b3);
            }
        }
    }

    l0s += __shfl_xor_sync(0xffffffffu, l0s, 1);
    l0s += __shfl_xor_sync(0xffffffffu, l0s, 2);
    l1s += __shfl_xor_sync(0xffffffffu, l1s, 1);
    l1s += __shfl_xor_sync(0xffffffffu, l1s, 2);
    float i0 = 1.0f / l0s, i1 = 1.0f / l1s;

    const int grow = q0 + warp * 16 + (lane >> 2);
    #pragma unroll
    for (int df = 0; df < 8; df++) {
        int col = hoff + df * 8 + 2 * (lane & 3);
        *(float2*)(O + (size_t)grow * DM + col) =
            make_float2(o[df][0] * i0, o[df][1] * i0);
        *(float2*)(O + (size_t)(grow + 8) * DM + col) =
            make_float2(o[df][2] * i1, o[df][3] * i1);
    }
}

// ---------------------------------------------------------------------------
extern "C" void kernel_launch(void* const* d_in, const int* in_sizes, int n_in,
                              void* d_out, int out_size)
{
    const float* query = (const float*)d_in[0];
    const float* key   = (const float*)d_in[1];
    const float* value = (const float*)d_in[2];
    const float* W_q   = (const float*)d_in[3];
    const float* b_q   = (const float*)d_in[4];
    const float* W_k   = (const float*)d_in[5];
    const float* b_k   = (const float*)d_in[6];
    const float* W_v   = (const float*)d_in[7];
    const float* b_v   = (const float*)d_in[8];
    const float* W_o   = (const float*)d_in[9];
    const float* b_o   = (const float*)d_in[10];
    float* out = (float*)d_out;

    __half *Qp, *Kp, *Vp;
    float *Ap;
    cudaGetSymbolAddress((void**)&Qp, g_Qs);
    cudaGetSymbolAddress((void**)&Kp, g_K);
    cudaGetSymbolAddress((void**)&Vp, g_V);
    cudaGetSymbolAddress((void**)&Ap, g_attn);

    const float SC = 0.125f * 1.4426950408889634f;   // 1/sqrt(64) * log2(e)

    const int gsmem = 2 * GBUF_B;                    // 81920 B
    const int fsmem = NSTAGE * STAGE_B;              // 55296 B
    static int attr_set = 0;
    if (!attr_set) {
        cudaFuncSetAttribute(gemm_split<0>, cudaFuncAttributeMaxDynamicSharedMemorySize, gsmem);
        cudaFuncSetAttribute(gemm_split<2>, cudaFuncAttributeMaxDynamicSharedMemorySize, gsmem);
        cudaFuncSetAttribute(fattn_kernel, cudaFuncAttributeMaxDynamicSharedMemorySize, fsmem);
        attr_set = 1;
    }

    dim3 ggrd(DM / 128, SEQ / 128);
    gemm_split<2><<<ggrd, 256, gsmem>>>(query, W_q, b_q, Qp, SC,   SEQ, DM, DM);
    gemm_split<2><<<ggrd, 256, gsmem>>>(key,   W_k, b_k, Kp, 1.0f, SEQ, DM, DM);
    gemm_split<2><<<ggrd, 256, gsmem>>>(value, W_v, b_v, Vp, 1.0f, SEQ, DM, DM);

    dim3 agrd(SEQ / 128, NH);
    fattn_kernel<<<agrd, 256, fsmem>>>(Qp, Kp, Vp, Ap);

    gemm_split<0><<<ggrd, 256, gsmem>>>(Ap, W_o, b_o, out, 1.0f, SEQ, DM, DM);
}

// round 11
// speedup vs baseline: 2.0826x; 1.2129x over previous
#include <cuda_runtime.h>
#include <cuda_bf16.h>
#include <cuda_fp16.h>
#include <math.h>

#define SEQ 4096
#define DM  1024
#define NH  16
#define DK  64

// Scratch (allocation-guard-safe device globals)
__device__ __half g_Qs[SEQ * DM];    // Q fp16, pre-scaled by 1/sqrt(dk)*log2(e)
__device__ __half g_K[SEQ * DM];     // K fp16
__device__ __half g_V[SEQ * DM];     // V fp16
__device__ float  g_attn[SEQ * DM];

// ---------------------------------------------------------------------------
// PTX helpers
// ---------------------------------------------------------------------------
__device__ __forceinline__ void mma_bf16(float* c, const unsigned* a,
                                         unsigned b0, unsigned b1) {
    asm volatile(
        "mma.sync.aligned.m16n8k16.row.col.f32.bf16.bf16.f32 "
        "{%0,%1,%2,%3}, {%4,%5,%6,%7}, {%8,%9}, {%0,%1,%2,%3};"
        : "+f"(c[0]), "+f"(c[1]), "+f"(c[2]), "+f"(c[3])
        : "r"(a[0]), "r"(a[1]), "r"(a[2]), "r"(a[3]), "r"(b0), "r"(b1));
}
__device__ __forceinline__ void mma_f16(float* c, const unsigned* a,
                                        unsigned b0, unsigned b1) {
    asm volatile(
        "mma.sync.aligned.m16n8k16.row.col.f32.f16.f16.f32 "
        "{%0,%1,%2,%3}, {%4,%5,%6,%7}, {%8,%9}, {%0,%1,%2,%3};"
        : "+f"(c[0]), "+f"(c[1]), "+f"(c[2]), "+f"(c[3])
        : "r"(a[0]), "r"(a[1]), "r"(a[2]), "r"(a[3]), "r"(b0), "r"(b1));
}
__device__ __forceinline__ void ldsm_x4(unsigned& r0, unsigned& r1,
                                        unsigned& r2, unsigned& r3, unsigned a) {
    asm volatile("ldmatrix.sync.aligned.m8n8.x4.shared.b16 {%0,%1,%2,%3}, [%4];"
                 : "=r"(r0), "=r"(r1), "=r"(r2), "=r"(r3) : "r"(a));
}
__device__ __forceinline__ void ldsm_x4_t(unsigned& r0, unsigned& r1,
                                          unsigned& r2, unsigned& r3, unsigned a) {
    asm volatile("ldmatrix.sync.aligned.m8n8.x4.trans.shared.b16 {%0,%1,%2,%3}, [%4];"
                 : "=r"(r0), "=r"(r1), "=r"(r2), "=r"(r3) : "r"(a));
}
__device__ __forceinline__ unsigned pack_f16(float lo, float hi) {
    unsigned r; asm("cvt.rn.f16x2.f32 %0, %1, %2;" : "=r"(r) : "f"(hi), "f"(lo));
    return r;
}
__device__ __forceinline__ float ex2(float x) {
    float r; asm("ex2.approx.ftz.f32 %0, %1;" : "=f"(r) : "f"(x)); return r;
}
__device__ __forceinline__ void bsplit(float2 f, unsigned& hi, unsigned& lo) {
    __nv_bfloat162 h = __float22bfloat162_rn(f);
    float2 hf = __bfloat1622float2(h);
    __nv_bfloat162 l = __float22bfloat162_rn(make_float2(f.x - hf.x, f.y - hf.y));
    hi = *(unsigned*)&h;
    lo = *(unsigned*)&l;
}
__device__ __forceinline__ void cp16(unsigned dst, const void* src) {
    asm volatile("cp.async.cg.shared.global [%0], [%1], 16;"
                 :: "r"(dst), "l"(src));
}

// ---------------------------------------------------------------------------
// Shared tiling constants (both GEMMs)
// ---------------------------------------------------------------------------
#define GP2 40                        // plane row stride in halves (80 B)
#define PLANE_B (128 * GP2 * 2)       // 10240 B per plane
#define GBUF_B (4 * PLANE_B)          // split GEMM: Ah,Al,Bh,Bl per buffer
#define FBUF_B (2 * PLANE_B)          // f16 GEMM: A,B per buffer

// ---------------------------------------------------------------------------
// bf16-split tensor-core GEMM (validated; used for O-projection only).
// 3 MMAs per k16: Ah*Bh + Al*Bh + Ah*Bl. fp32 C output.
// ---------------------------------------------------------------------------
__global__ __launch_bounds__(256) void gemm_split(
    const float* __restrict__ A, const float* __restrict__ B,
    const float* __restrict__ bias, float* __restrict__ C,
    int M, int N, int Kd)
{
    extern __shared__ char dsm[];     // 2 * GBUF_B = 81920 B
    const unsigned sbase = (unsigned)__cvta_generic_to_shared(dsm);

    const int tid  = threadIdx.x;
    const int lane = tid & 31;
    const int warp = tid >> 5;
    const int wy = warp & 3;
    const int wx = warp >> 2;
    const int bm0 = blockIdx.y * 128;
    const int bn0 = blockIdx.x * 128;

    const int lr = tid >> 3;
    const int lc = (tid & 7) << 2;

    float acc[2][8][4];
    #pragma unroll
    for (int mf = 0; mf < 2; mf++)
        #pragma unroll
        for (int nf = 0; nf < 8; nf++)
            #pragma unroll
            for (int i = 0; i < 4; i++) acc[mf][nf][i] = 0.0f;

    float4 ra[4], rb[4];

    auto store_split = [&](int buf) {
        char* bb = dsm + buf * GBUF_B;
        #pragma unroll
        for (int p = 0; p < 4; p++) {
            int row = lr + 32 * p;
            int off = (row * GP2 + lc) * 2;
            unsigned h0, l0, h1, l1;
            bsplit(make_float2(ra[p].x, ra[p].y), h0, l0);
            bsplit(make_float2(ra[p].z, ra[p].w), h1, l1);
            *(uint2*)(bb + off)               = make_uint2(h0, h1);
            *(uint2*)(bb + PLANE_B + off)     = make_uint2(l0, l1);
            bsplit(make_float2(rb[p].x, rb[p].y), h0, l0);
            bsplit(make_float2(rb[p].z, rb[p].w), h1, l1);
            *(uint2*)(bb + 2 * PLANE_B + off) = make_uint2(h0, h1);
            *(uint2*)(bb + 3 * PLANE_B + off) = make_uint2(l0, l1);
        }
    };

    #pragma unroll
    for (int p = 0; p < 4; p++) {
        int row = lr + 32 * p;
        ra[p] = *(const float4*)(A + (size_t)(bm0 + row) * Kd + lc);
        rb[p] = *(const float4*)(B + (size_t)(bn0 + row) * Kd + lc);
    }
    store_split(0);
    __syncthreads();

    const int a_row = (lane & 15);
    const int a_chk = 8 * (lane >> 4);
    const int b_row = 8 * ((lane >> 4) & 1) + (lane & 7);
    const int b_chk = 8 * ((lane >> 3) & 1);

    const int NT = Kd >> 5;
    for (int kt = 0; kt < NT; kt++) {
        const int buf = kt & 1;
        const unsigned bb = sbase + buf * GBUF_B;

        if (kt + 1 < NT) {
            #pragma unroll
            for (int p = 0; p < 4; p++) {
                int row = lr + 32 * p;
                ra[p] = *(const float4*)(A + (size_t)(bm0 + row) * Kd + (kt + 1) * 32 + lc);
                rb[p] = *(const float4*)(B + (size_t)(bn0 + row) * Kd + (kt + 1) * 32 + lc);
            }
        }

        #pragma unroll
        for (int ks = 0; ks < 2; ks++) {
            const int ko = ks * 16;
            unsigned ah[2][4], al[2][4];
            #pragma unroll
            for (int mf = 0; mf < 2; mf++) {
                unsigned addr = bb +
                    (unsigned)(((wy * 32 + mf * 16 + a_row) * GP2 + ko + a_chk) * 2);
                ldsm_x4(ah[mf][0], ah[mf][1], ah[mf][2], ah[mf][3], addr);
                ldsm_x4(al[mf][0], al[mf][1], al[mf][2], al[mf][3], addr + PLANE_B);
            }
            #pragma unroll
            for (int nfp = 0; nfp < 4; nfp++) {
                unsigned baddr = bb + 2 * PLANE_B +
                    (unsigned)(((wx * 64 + 16 * nfp + b_row) * GP2 + ko + b_chk) * 2);
                unsigned bh0, bh1, bh2, bh3, bl0, bl1, bl2, bl3;
                ldsm_x4(bh0, bh1, bh2, bh3, baddr);
                ldsm_x4(bl0, bl1, bl2, bl3, baddr + PLANE_B);
                #pragma unroll
                for (int mf = 0; mf < 2; mf++) {
                    mma_bf16(acc[mf][2 * nfp],     ah[mf], bh0, bh1);
                    mma_bf16(acc[mf][2 * nfp],     al[mf], bh0, bh1);
                    mma_bf16(acc[mf][2 * nfp],     ah[mf], bl0, bl1);
                    mma_bf16(acc[mf][2 * nfp + 1], ah[mf], bh2, bh3);
                    mma_bf16(acc[mf][2 * nfp + 1], al[mf], bh2, bh3);
                    mma_bf16(acc[mf][2 * nfp + 1], ah[mf], bl2, bl3);
                }
            }
        }

        if (kt + 1 < NT) {
            __syncthreads();
            store_split(1 - buf);
        }
        __syncthreads();
    }

    #pragma unroll
    for (int mf = 0; mf < 2; mf++) {
        #pragma unroll
        for (int nf = 0; nf < 8; nf++) {
            int r  = bm0 + wy * 32 + mf * 16 + (lane >> 2);
            int cc = bn0 + wx * 64 + nf * 8 + 2 * (lane & 3);
            float bv0 = bias[cc], bv1 = bias[cc + 1];
            *(float2*)(C + (size_t)r * N + cc) =
                make_float2(acc[mf][nf][0] + bv0, acc[mf][nf][1] + bv1);
            *(float2*)(C + (size_t)(r + 8) * N + cc) =
                make_float2(acc[mf][nf][2] + bv0, acc[mf][nf][3] + bv1);
        }
    }
}

// ---------------------------------------------------------------------------
// Single-pass fp16 tensor-core GEMM (Q/K/V projections).
// C_f16 = ((A @ B^T) + bias) * oscale. 1 MMA per k16 step.
// Smem: 2 fp16 planes (A, B) per buffer -> 2 CTAs/SM.
// ---------------------------------------------------------------------------
__global__ __launch_bounds__(256, 2) void gemm_f16(
    const float* __restrict__ A, const float* __restrict__ B,
    const float* __restrict__ bias, __half* __restrict__ C,
    float oscale, int M, int N, int Kd)
{
    extern __shared__ char dsm[];     // 2 * FBUF_B = 40960 B
    const unsigned sbase = (unsigned)__cvta_generic_to_shared(dsm);

    const int tid  = threadIdx.x;
    const int lane = tid & 31;
    const int warp = tid >> 5;
    const int wy = warp & 3;
    const int wx = warp >> 2;
    const int bm0 = blockIdx.y * 128;
    const int bn0 = blockIdx.x * 128;

    const int lr = tid >> 3;
    const int lc = (tid & 7) << 2;

    float acc[2][8][4];
    #pragma unroll
    for (int mf = 0; mf < 2; mf++)
        #pragma unroll
        for (int nf = 0; nf < 8; nf++)
            #pragma unroll
            for (int i = 0; i < 4; i++) acc[mf][nf][i] = 0.0f;

    float4 ra[4], rb[4];

    auto store_f16 = [&](int buf) {
        char* bb = dsm + buf * FBUF_B;
        #pragma unroll
        for (int p = 0; p < 4; p++) {
            int row = lr + 32 * p;
            int off = (row * GP2 + lc) * 2;
            *(uint2*)(bb + off) = make_uint2(
                pack_f16(ra[p].x, ra[p].y), pack_f16(ra[p].z, ra[p].w));
            *(uint2*)(bb + PLANE_B + off) = make_uint2(
                pack_f16(rb[p].x, rb[p].y), pack_f16(rb[p].z, rb[p].w));
        }
    };

    #pragma unroll
    for (int p = 0; p < 4; p++) {
        int row = lr + 32 * p;
        ra[p] = *(const float4*)(A + (size_t)(bm0 + row) * Kd + lc);
        rb[p] = *(const float4*)(B + (size_t)(bn0 + row) * Kd + lc);
    }
    store_f16(0);
    __syncthreads();

    const int a_row = (lane & 15);
    const int a_chk = 8 * (lane >> 4);
    const int b_row = 8 * ((lane >> 4) & 1) + (lane & 7);
    const int b_chk = 8 * ((lane >> 3) & 1);

    const int NT = Kd >> 5;
    for (int kt = 0; kt < NT; kt++) {
        const int buf = kt & 1;
        const unsigned bb = sbase + buf * FBUF_B;

        if (kt + 1 < NT) {
            #pragma unroll
            for (int p = 0; p < 4; p++) {
                int row = lr + 32 * p;
                ra[p] = *(const float4*)(A + (size_t)(bm0 + row) * Kd + (kt + 1) * 32 + lc);
                rb[p] = *(const float4*)(B + (size_t)(bn0 + row) * Kd + (kt + 1) * 32 + lc);
            }
        }

        #pragma unroll
        for (int ks = 0; ks < 2; ks++) {
            const int ko = ks * 16;
            unsigned af[2][4];
            #pragma unroll
            for (int mf = 0; mf < 2; mf++) {
                unsigned addr = bb +
                    (unsigned)(((wy * 32 + mf * 16 + a_row) * GP2 + ko + a_chk) * 2);
                ldsm_x4(af[mf][0], af[mf][1], af[mf][2], af[mf][3], addr);
            }
            #pragma unroll
            for (int nfp = 0; nfp < 4; nfp++) {
                unsigned baddr = bb + PLANE_B +
                    (unsigned)(((wx * 64 + 16 * nfp + b_row) * GP2 + ko + b_chk) * 2);
                unsigned b0, b1, b2, b3;
                ldsm_x4(b0, b1, b2, b3, baddr);
                #pragma unroll
                for (int mf = 0; mf < 2; mf++) {
                    mma_f16(acc[mf][2 * nfp],     af[mf], b0, b1);
                    mma_f16(acc[mf][2 * nfp + 1], af[mf], b2, b3);
                }
            }
        }

        if (kt + 1 < NT) {
            __syncthreads();
            store_f16(1 - buf);
        }
        __syncthreads();
    }

    #pragma unroll
    for (int mf = 0; mf < 2; mf++) {
        #pragma unroll
        for (int nf = 0; nf < 8; nf++) {
            int r  = bm0 + wy * 32 + mf * 16 + (lane >> 2);
            int cc = bn0 + wx * 64 + nf * 8 + 2 * (lane & 3);
            float bv0 = bias[cc], bv1 = bias[cc + 1];
            *(unsigned*)(C + (size_t)r * N + cc) =
                pack_f16((acc[mf][nf][0] + bv0) * oscale,
                         (acc[mf][nf][1] + bv1) * oscale);
            *(unsigned*)(C + (size_t)(r + 8) * N + cc) =
                pack_f16((acc[mf][nf][2] + bv0) * oscale,
                         (acc[mf][nf][3] + bv1) * oscale);
        }
    }
}

// ---------------------------------------------------------------------------
// Tensor-core flash attention, v4 (unchanged — validated).
// ---------------------------------------------------------------------------
#define KST 72
#define TILE_B (64 * KST * 2)
#define STAGE_B (2 * TILE_B)
#define NSTAGE 3
#define QROWB (KST * 2)

__global__ __launch_bounds__(256, 2) void fattn_kernel(
    const __half* __restrict__ Q, const __half* __restrict__ K,
    const __half* __restrict__ V, float* __restrict__ O)
{
    extern __shared__ char dsm[];

    const int tid  = threadIdx.x;
    const int lane = tid & 31;
    const int warp = tid >> 5;
    const int h    = blockIdx.y;
    const int q0   = blockIdx.x * 128;
    const int hoff = h * DK;

    const unsigned smem_base = (unsigned)__cvta_generic_to_shared(dsm);

    {
        int qr = tid >> 1;
        int qc = (tid & 1) * 64;
        const char* src = (const char*)(Q + (size_t)(q0 + qr) * DM + hoff) + qc;
        unsigned dst = smem_base + qr * QROWB + qc;
        cp16(dst, src);  cp16(dst + 16, src + 16);
        cp16(dst + 32, src + 32);  cp16(dst + 48, src + 48);
    }
    asm volatile("cp.async.commit_group;");
    asm volatile("cp.async.wait_group 0;");
    __syncthreads();

    unsigned qf[4][4];
    {
        const unsigned qrow = warp * 16 + (lane & 15);
        #pragma unroll
        for (int s4 = 0; s4 < 4; s4++) {
            unsigned addr = smem_base + qrow * QROWB + (s4 * 16 + 8 * (lane >> 4)) * 2;
            ldsm_x4(qf[s4][0], qf[s4][1], qf[s4][2], qf[s4][3], addr);
        }
    }
    __syncthreads();

    const int lrow = tid >> 2;
    const int lcb  = (tid & 3) * 32;
    const char* srcK = (const char*)(K + (size_t)lrow * DM + hoff) + lcb;
    const char* srcV = (const char*)(V + (size_t)lrow * DM + hoff) + lcb;
    const unsigned drow = smem_base + lrow * (KST * 2) + lcb;

    auto load_stage = [&](int t, int sbuf) {
        size_t goff = (size_t)t * 64 * DM * 2;
        unsigned d = drow + sbuf * STAGE_B;
        cp16(d, srcK + goff);           cp16(d + 16, srcK + goff + 16);
        cp16(d + TILE_B, srcV + goff);  cp16(d + TILE_B + 16, srcV + goff + 16);
    };

    const int NTILE = SEQ / 64;
    load_stage(0, 0);
    asm volatile("cp.async.commit_group;");
    load_stage(1, 1);
    asm volatile("cp.async.commit_group;");

    const unsigned k_off = ((8 * ((lane >> 4) & 1) + (lane & 7)) * KST
                            + 8 * ((lane >> 3) & 1)) * 2;
    const unsigned v_off = ((8 * ((lane >> 3) & 1) + (lane & 7)) * KST
                            + 8 * (lane >> 4)) * 2;

    float o[8][4];
    #pragma unroll
    for (int df = 0; df < 8; df++)
        #pragma unroll
        for (int i = 0; i < 4; i++) o[df][i] = 0.0f;
    float m0 = -1e30f, m1 = -1e30f, l0s = 0.0f, l1s = 0.0f;

    for (int t = 0; t < NTILE; t++) {
        const int buf = t % NSTAGE;
        const unsigned stage = smem_base + buf * STAGE_B;

        asm volatile("cp.async.wait_group 1;");
        __syncthreads();

        if (t + 2 < NTILE) load_stage(t + 2, (t + 2) % NSTAGE);
        asm volatile("cp.async.commit_group;");

        float s[8][4];
        #pragma unroll
        for (int nf = 0; nf < 8; nf++)
            #pragma unroll
            for (int i = 0; i < 4; i++) s[nf][i] = 0.0f;

        #pragma unroll
        for (int s4 = 0; s4 < 4; s4++) {
            const int d0 = 16 * s4;
            #pragma unroll
            for (int nfp = 0; nfp < 4; nfp++) {
                const unsigned off = (unsigned)((16 * nfp) * KST + d0) * 2 + k_off;
                unsigned h0, h1, h2, h3;
                ldsm_x4(h0, h1, h2, h3, stage + off);
                mma_f16(s[2 * nfp],     qf[s4], h0, h1);
                mma_f16(s[2 * nfp + 1], qf[s4], h2, h3);
            }
        }

        float mx0 = -1e30f, mx1 = -1e30f;
        #pragma unroll
        for (int nf = 0; nf < 8; nf++) {
            mx0 = fmaxf(mx0, fmaxf(s[nf][0], s[nf][1]));
            mx1 = fmaxf(mx1, fmaxf(s[nf][2], s[nf][3]));
        }
        mx0 = fmaxf(mx0, __shfl_xor_sync(0xffffffffu, mx0, 1));
        mx0 = fmaxf(mx0, __shfl_xor_sync(0xffffffffu, mx0, 2));
        mx1 = fmaxf(mx1, __shfl_xor_sync(0xffffffffu, mx1, 1));
        mx1 = fmaxf(mx1, __shfl_xor_sync(0xffffffffu, mx1, 2));

        float nm0 = fmaxf(m0, mx0), nm1 = fmaxf(m1, mx1);
        float a0 = ex2(m0 - nm0), a1 = ex2(m1 - nm1);
        m0 = nm0; m1 = nm1;

        unsigned pp[8][2];
        float ps0 = 0.0f, ps1 = 0.0f;
        #pragma unroll
        for (int nf = 0; nf < 8; nf++) {
            float p0 = ex2(s[nf][0] - nm0);
            float p1 = ex2(s[nf][1] - nm0);
            float p2 = ex2(s[nf][2] - nm1);
            float p3 = ex2(s[nf][3] - nm1);
            ps0 += p0 + p1;
            ps1 += p2 + p3;
            pp[nf][0] = pack_f16(p0, p1);
            pp[nf][1] = pack_f16(p2, p3);
        }
        l0s = l0s * a0 + ps0;
        l1s = l1s * a1 + ps1;

        #pragma unroll
        for (int df = 0; df < 8; df++) {
            o[df][0] *= a0; o[df][1] *= a0;
            o[df][2] *= a1; o[df][3] *= a1;
        }

        #pragma unroll
        for (int kf2 = 0; kf2 < 4; kf2++) {
            unsigned af[4];
            af[0] = pp[2 * kf2][0];
            af[1] = pp[2 * kf2][1];
            af[2] = pp[2 * kf2 + 1][0];
            af[3] = pp[2 * kf2 + 1][1];
            #pragma unroll
            for (int dfp = 0; dfp < 4; dfp++) {
                const unsigned off = (unsigned)((16 * kf2) * KST + 16 * dfp) * 2 + v_off;
                unsigned b0, b1, b2, b3;
                ldsm_x4_t(b0, b1, b2, b3, stage + TILE_B + off);
                mma_f16(o[2 * dfp],     af, b0, b1);
                mma_f16(o[2 * dfp + 1], af, b2, b3);
            }
        }
    }

    l0s += __shfl_xor_sync(0xffffffffu, l0s, 1);
    l0s += __shfl_xor_sync(0xffffffffu, l0s, 2);
    l1s += __shfl_xor_sync(0xffffffffu, l1s, 1);
    l1s += __shfl_xor_sync(0xffffffffu, l1s, 2);
    float i0 = 1.0f / l0s, i1 = 1.0f / l1s;

    const int grow = q0 + warp * 16 + (lane >> 2);
    #pragma unroll
    for (int df = 0; df < 8; df++) {
        int col = hoff + df * 8 + 2 * (lane & 3);
        *(float2*)(O + (size_t)grow * DM + col) =
            make_float2(o[df][0] * i0, o[df][1] * i0);
        *(float2*)(O + (size_t)(grow + 8) * DM + col) =
            make_float2(o[df][2] * i1, o[df][3] * i1);
    }
}

// ---------------------------------------------------------------------------
extern "C" void kernel_launch(void* const* d_in, const int* in_sizes, int n_in,
                              void* d_out, int out_size)
{
    const float* query = (const float*)d_in[0];
    const float* key   = (const float*)d_in[1];
    const float* value = (const float*)d_in[2];
    const float* W_q   = (const float*)d_in[3];
    const float* b_q   = (const float*)d_in[4];
    const float* W_k   = (const float*)d_in[5];
    const float* b_k   = (const float*)d_in[6];
    const float* W_v   = (const float*)d_in[7];
    const float* b_v   = (const float*)d_in[8];
    const float* W_o   = (const float*)d_in[9];
    const float* b_o   = (const float*)d_in[10];
    float* out = (float*)d_out;

    __half *Qp, *Kp, *Vp;
    float *Ap;
    cudaGetSymbolAddress((void**)&Qp, g_Qs);
    cudaGetSymbolAddress((void**)&Kp, g_K);
    cudaGetSymbolAddress((void**)&Vp, g_V);
    cudaGetSymbolAddress((void**)&Ap, g_attn);

    const float SC = 0.125f * 1.4426950408889634f;   // 1/sqrt(64) * log2(e)

    const int gsmem = 2 * GBUF_B;                    // 81920 B
    const int psmem = 2 * FBUF_B;                    // 40960 B
    const int fsmem = NSTAGE * STAGE_B;              // 55296 B
    static int attr_set = 0;
    if (!attr_set) {
        cudaFuncSetAttribute(gemm_split, cudaFuncAttributeMaxDynamicSharedMemorySize, gsmem);
        cudaFuncSetAttribute(gemm_f16, cudaFuncAttributeMaxDynamicSharedMemorySize, psmem);
        cudaFuncSetAttribute(fattn_kernel, cudaFuncAttributeMaxDynamicSharedMemorySize, fsmem);
        attr_set = 1;
    }

    dim3 ggrd(DM / 128, SEQ / 128);
    gemm_f16<<<ggrd, 256, psmem>>>(query, W_q, b_q, Qp, SC,   SEQ, DM, DM);
    gemm_f16<<<ggrd, 256, psmem>>>(key,   W_k, b_k, Kp, 1.0f, SEQ, DM, DM);
    gemm_f16<<<ggrd, 256, psmem>>>(value, W_v, b_v, Vp, 1.0f, SEQ, DM, DM);

    dim3 agrd(SEQ / 128, NH);
    fattn_kernel<<<agrd, 256, fsmem>>>(Qp, Kp, Vp, Ap);

    gemm_split<<<ggrd, 256, gsmem>>>(Ap, W_o, b_o, out, SEQ, DM, DM);
}

// round 12
// speedup vs baseline: 2.1201x; 1.0180x over previous
#include <cuda_runtime.h>
#include <cuda_bf16.h>
#include <cuda_fp16.h>
#include <math.h>

#define SEQ 4096
#define DM  1024
#define NH  16
#define DK  64

// Scratch (allocation-guard-safe device globals)
__device__ __half g_qi[SEQ * DM];    // fp16 copies of inputs
__device__ __half g_ki[SEQ * DM];
__device__ __half g_vi[SEQ * DM];
__device__ __half g_wq[DM * DM];     // fp16 copies of weights
__device__ __half g_wk[DM * DM];
__device__ __half g_wv[DM * DM];
__device__ __half g_Qs[SEQ * DM];    // Q projection, pre-scaled
__device__ __half g_K[SEQ * DM];     // K projection
__device__ __half g_V[SEQ * DM];     // V projection
__device__ float  g_attn[SEQ * DM];

// ---------------------------------------------------------------------------
// PTX helpers
// ---------------------------------------------------------------------------
__device__ __forceinline__ void mma_bf16(float* c, const unsigned* a,
                                         unsigned b0, unsigned b1) {
    asm volatile(
        "mma.sync.aligned.m16n8k16.row.col.f32.bf16.bf16.f32 "
        "{%0,%1,%2,%3}, {%4,%5,%6,%7}, {%8,%9}, {%0,%1,%2,%3};"
        : "+f"(c[0]), "+f"(c[1]), "+f"(c[2]), "+f"(c[3])
        : "r"(a[0]), "r"(a[1]), "r"(a[2]), "r"(a[3]), "r"(b0), "r"(b1));
}
__device__ __forceinline__ void mma_f16(float* c, const unsigned* a,
                                        unsigned b0, unsigned b1) {
    asm volatile(
        "mma.sync.aligned.m16n8k16.row.col.f32.f16.f16.f32 "
        "{%0,%1,%2,%3}, {%4,%5,%6,%7}, {%8,%9}, {%0,%1,%2,%3};"
        : "+f"(c[0]), "+f"(c[1]), "+f"(c[2]), "+f"(c[3])
        : "r"(a[0]), "r"(a[1]), "r"(a[2]), "r"(a[3]), "r"(b0), "r"(b1));
}
__device__ __forceinline__ void ldsm_x4(unsigned& r0, unsigned& r1,
                                        unsigned& r2, unsigned& r3, unsigned a) {
    asm volatile("ldmatrix.sync.aligned.m8n8.x4.shared.b16 {%0,%1,%2,%3}, [%4];"
                 : "=r"(r0), "=r"(r1), "=r"(r2), "=r"(r3) : "r"(a));
}
__device__ __forceinline__ void ldsm_x4_t(unsigned& r0, unsigned& r1,
                                          unsigned& r2, unsigned& r3, unsigned a) {
    asm volatile("ldmatrix.sync.aligned.m8n8.x4.trans.shared.b16 {%0,%1,%2,%3}, [%4];"
                 : "=r"(r0), "=r"(r1), "=r"(r2), "=r"(r3) : "r"(a));
}
__device__ __forceinline__ unsigned pack_f16(float lo, float hi) {
    unsigned r; asm("cvt.rn.f16x2.f32 %0, %1, %2;" : "=r"(r) : "f"(hi), "f"(lo));
    return r;
}
__device__ __forceinline__ float ex2(float x) {
    float r; asm("ex2.approx.ftz.f32 %0, %1;" : "=f"(r) : "f"(x)); return r;
}
__device__ __forceinline__ void bsplit(float2 f, unsigned& hi, unsigned& lo) {
    __nv_bfloat162 h = __float22bfloat162_rn(f);
    float2 hf = __bfloat1622float2(h);
    __nv_bfloat162 l = __float22bfloat162_rn(make_float2(f.x - hf.x, f.y - hf.y));
    hi = *(unsigned*)&h;
    lo = *(unsigned*)&l;
}
__device__ __forceinline__ void cp16(unsigned dst, const void* src) {
    asm volatile("cp.async.cg.shared.global [%0], [%1], 16;"
                 :: "r"(dst), "l"(src));
}

// ---------------------------------------------------------------------------
// fp32 -> fp16 batch convert (3 tensors of equal element count, y selects)
// ---------------------------------------------------------------------------
__global__ __launch_bounds__(256) void cvt3_kernel(
    const float* __restrict__ a, const float* __restrict__ b,
    const float* __restrict__ c, __half* oa, __half* ob, __half* oc)
{
    const float* in = (blockIdx.y == 0) ? a : (blockIdx.y == 1) ? b : c;
    __half* out = (blockIdx.y == 0) ? oa : (blockIdx.y == 1) ? ob : oc;
    int i = (blockIdx.x * 256 + threadIdx.x) * 4;
    float4 v = *(const float4*)(in + i);
    *(uint2*)(out + i) = make_uint2(pack_f16(v.x, v.y), pack_f16(v.z, v.w));
}

// ---------------------------------------------------------------------------
// Shared tiling constants
// ---------------------------------------------------------------------------
#define GP2 40                        // plane row stride in halves (80 B)
#define PLANE_B (128 * GP2 * 2)       // 10240 B per plane
#define GBUF_B (4 * PLANE_B)          // split GEMM buffer (Ah,Al,Bh,Bl)
#define FSTG_B (2 * PLANE_B)          // f16 GEMM stage (A,B)
#define FNST 3                        // f16 GEMM pipeline stages

// ---------------------------------------------------------------------------
// bf16-split tensor-core GEMM (validated; O-projection only).
// ---------------------------------------------------------------------------
__global__ __launch_bounds__(256) void gemm_split(
    const float* __restrict__ A, const float* __restrict__ B,
    const float* __restrict__ bias, float* __restrict__ C,
    int M, int N, int Kd)
{
    extern __shared__ char dsm[];
    const unsigned sbase = (unsigned)__cvta_generic_to_shared(dsm);

    const int tid  = threadIdx.x;
    const int lane = tid & 31;
    const int warp = tid >> 5;
    const int wy = warp & 3;
    const int wx = warp >> 2;
    const int bm0 = blockIdx.y * 128;
    const int bn0 = blockIdx.x * 128;

    const int lr = tid >> 3;
    const int lc = (tid & 7) << 2;

    float acc[2][8][4];
    #pragma unroll
    for (int mf = 0; mf < 2; mf++)
        #pragma unroll
        for (int nf = 0; nf < 8; nf++)
            #pragma unroll
            for (int i = 0; i < 4; i++) acc[mf][nf][i] = 0.0f;

    float4 ra[4], rb[4];

    auto store_split = [&](int buf) {
        char* bb = dsm + buf * GBUF_B;
        #pragma unroll
        for (int p = 0; p < 4; p++) {
            int row = lr + 32 * p;
            int off = (row * GP2 + lc) * 2;
            unsigned h0, l0, h1, l1;
            bsplit(make_float2(ra[p].x, ra[p].y), h0, l0);
            bsplit(make_float2(ra[p].z, ra[p].w), h1, l1);
            *(uint2*)(bb + off)               = make_uint2(h0, h1);
            *(uint2*)(bb + PLANE_B + off)     = make_uint2(l0, l1);
            bsplit(make_float2(rb[p].x, rb[p].y), h0, l0);
            bsplit(make_float2(rb[p].z, rb[p].w), h1, l1);
            *(uint2*)(bb + 2 * PLANE_B + off) = make_uint2(h0, h1);
            *(uint2*)(bb + 3 * PLANE_B + off) = make_uint2(l0, l1);
        }
    };

    #pragma unroll
    for (int p = 0; p < 4; p++) {
        int row = lr + 32 * p;
        ra[p] = *(const float4*)(A + (size_t)(bm0 + row) * Kd + lc);
        rb[p] = *(const float4*)(B + (size_t)(bn0 + row) * Kd + lc);
    }
    store_split(0);
    __syncthreads();

    const int a_row = (lane & 15);
    const int a_chk = 8 * (lane >> 4);
    const int b_row = 8 * ((lane >> 4) & 1) + (lane & 7);
    const int b_chk = 8 * ((lane >> 3) & 1);

    const int NT = Kd >> 5;
    for (int kt = 0; kt < NT; kt++) {
        const int buf = kt & 1;
        const unsigned bb = sbase + buf * GBUF_B;

        if (kt + 1 < NT) {
            #pragma unroll
            for (int p = 0; p < 4; p++) {
                int row = lr + 32 * p;
                ra[p] = *(const float4*)(A + (size_t)(bm0 + row) * Kd + (kt + 1) * 32 + lc);
                rb[p] = *(const float4*)(B + (size_t)(bn0 + row) * Kd + (kt + 1) * 32 + lc);
            }
        }

        #pragma unroll
        for (int ks = 0; ks < 2; ks++) {
            const int ko = ks * 16;
            unsigned ah[2][4], al[2][4];
            #pragma unroll
            for (int mf = 0; mf < 2; mf++) {
                unsigned addr = bb +
                    (unsigned)(((wy * 32 + mf * 16 + a_row) * GP2 + ko + a_chk) * 2);
                ldsm_x4(ah[mf][0], ah[mf][1], ah[mf][2], ah[mf][3], addr);
                ldsm_x4(al[mf][0], al[mf][1], al[mf][2], al[mf][3], addr + PLANE_B);
            }
            #pragma unroll
            for (int nfp = 0; nfp < 4; nfp++) {
                unsigned baddr = bb + 2 * PLANE_B +
                    (unsigned)(((wx * 64 + 16 * nfp + b_row) * GP2 + ko + b_chk) * 2);
                unsigned bh0, bh1, bh2, bh3, bl0, bl1, bl2, bl3;
                ldsm_x4(bh0, bh1, bh2, bh3, baddr);
                ldsm_x4(bl0, bl1, bl2, bl3, baddr + PLANE_B);
                #pragma unroll
                for (int mf = 0; mf < 2; mf++) {
                    mma_bf16(acc[mf][2 * nfp],     ah[mf], bh0, bh1);
                    mma_bf16(acc[mf][2 * nfp],     al[mf], bh0, bh1);
                    mma_bf16(acc[mf][2 * nfp],     ah[mf], bl0, bl1);
                    mma_bf16(acc[mf][2 * nfp + 1], ah[mf], bh2, bh3);
                    mma_bf16(acc[mf][2 * nfp + 1], al[mf], bh2, bh3);
                    mma_bf16(acc[mf][2 * nfp + 1], ah[mf], bl2, bl3);
                }
            }
        }

        if (kt + 1 < NT) {
            __syncthreads();
            store_split(1 - buf);
        }
        __syncthreads();
    }

    #pragma unroll
    for (int mf = 0; mf < 2; mf++) {
        #pragma unroll
        for (int nf = 0; nf < 8; nf++) {
            int r  = bm0 + wy * 32 + mf * 16 + (lane >> 2);
            int cc = bn0 + wx * 64 + nf * 8 + 2 * (lane & 3);
            float bv0 = bias[cc], bv1 = bias[cc + 1];
            *(float2*)(C + (size_t)r * N + cc) =
                make_float2(acc[mf][nf][0] + bv0, acc[mf][nf][1] + bv1);
            *(float2*)(C + (size_t)(r + 8) * N + cc) =
                make_float2(acc[mf][nf][2] + bv0, acc[mf][nf][3] + bv1);
        }
    }
}

// ---------------------------------------------------------------------------
// fp16 cp.async GEMM (Q/K/V projections): C_f16 = ((A@B^T)+bias)*oscale.
// A,B pre-converted fp16. 3-stage cp.async pipeline, no in-loop conversion.
// ---------------------------------------------------------------------------
__global__ __launch_bounds__(256, 2) void gemm_f16a(
    const __half* __restrict__ A, const __half* __restrict__ B,
    const float* __restrict__ bias, __half* __restrict__ C,
    float oscale, int M, int N, int Kd)
{
    extern __shared__ char dsm[];     // FNST * FSTG_B = 61440 B
    const unsigned sbase = (unsigned)__cvta_generic_to_shared(dsm);

    const int tid  = threadIdx.x;
    const int lane = tid & 31;
    const int warp = tid >> 5;
    const int wy = warp & 3;
    const int wx = warp >> 2;
    const int bm0 = blockIdx.y * 128;
    const int bn0 = blockIdx.x * 128;

    // loader: row = tid>>1 (0..127), 16-half chunk = (tid&1)*16
    const int lrow = tid >> 1;
    const int lch  = (tid & 1) * 16;
    const char* srcA = (const char*)(A + (size_t)(bm0 + lrow) * Kd + lch);
    const char* srcB = (const char*)(B + (size_t)(bn0 + lrow) * Kd + lch);
    const unsigned dOff = (unsigned)((lrow * GP2 + lch) * 2);

    auto load_stage = [&](int kt, int sb) {
        unsigned d = sbase + sb * FSTG_B + dOff;
        size_t g = (size_t)kt * 32 * 2;       // byte advance along K
        cp16(d, srcA + g);            cp16(d + 16, srcA + g + 16);
        cp16(d + PLANE_B, srcB + g);  cp16(d + PLANE_B + 16, srcB + g + 16);
    };

    float acc[2][8][4];
    #pragma unroll
    for (int mf = 0; mf < 2; mf++)
        #pragma unroll
        for (int nf = 0; nf < 8; nf++)
            #pragma unroll
            for (int i = 0; i < 4; i++) acc[mf][nf][i] = 0.0f;

    load_stage(0, 0);
    asm volatile("cp.async.commit_group;");
    load_stage(1, 1);
    asm volatile("cp.async.commit_group;");

    const int a_row = (lane & 15);
    const int a_chk = 8 * (lane >> 4);
    const int b_row = 8 * ((lane >> 4) & 1) + (lane & 7);
    const int b_chk = 8 * ((lane >> 3) & 1);

    const int NT = Kd >> 5;
    for (int kt = 0; kt < NT; kt++) {
        asm volatile("cp.async.wait_group 1;");
        __syncthreads();
        if (kt + 2 < NT) load_stage(kt + 2, (kt + 2) % FNST);
        asm volatile("cp.async.commit_group;");

        const unsigned bb = sbase + (kt % FNST) * FSTG_B;

        #pragma unroll
        for (int ks = 0; ks < 2; ks++) {
            const int ko = ks * 16;
            unsigned af[2][4];
            #pragma unroll
            for (int mf = 0; mf < 2; mf++) {
                unsigned addr = bb +
                    (unsigned)(((wy * 32 + mf * 16 + a_row) * GP2 + ko + a_chk) * 2);
                ldsm_x4(af[mf][0], af[mf][1], af[mf][2], af[mf][3], addr);
            }
            #pragma unroll
            for (int nfp = 0; nfp < 4; nfp++) {
                unsigned baddr = bb + PLANE_B +
                    (unsigned)(((wx * 64 + 16 * nfp + b_row) * GP2 + ko + b_chk) * 2);
                unsigned b0, b1, b2, b3;
                ldsm_x4(b0, b1, b2, b3, baddr);
                #pragma unroll
                for (int mf = 0; mf < 2; mf++) {
                    mma_f16(acc[mf][2 * nfp],     af[mf], b0, b1);
                    mma_f16(acc[mf][2 * nfp + 1], af[mf], b2, b3);
                }
            }
        }
    }

    #pragma unroll
    for (int mf = 0; mf < 2; mf++) {
        #pragma unroll
        for (int nf = 0; nf < 8; nf++) {
            int r  = bm0 + wy * 32 + mf * 16 + (lane >> 2);
            int cc = bn0 + wx * 64 + nf * 8 + 2 * (lane & 3);
            float bv0 = bias[cc], bv1 = bias[cc + 1];
            *(unsigned*)(C + (size_t)r * N + cc) =
                pack_f16((acc[mf][nf][0] + bv0) * oscale,
                         (acc[mf][nf][1] + bv1) * oscale);
            *(unsigned*)(C + (size_t)(r + 8) * N + cc) =
                pack_f16((acc[mf][nf][2] + bv0) * oscale,
                         (acc[mf][nf][3] + bv1) * oscale);
        }
    }
}

// ---------------------------------------------------------------------------
// Tensor-core flash attention v5: PV lagged one tile behind QK so softmax
// overlaps PV's tensor work. 4-stage cp.async pipeline.
// ---------------------------------------------------------------------------
#define KST 72
#define TILE_B (64 * KST * 2)
#define STAGE_B (2 * TILE_B)
#define NSTAGE 4
#define QROWB (KST * 2)

__global__ __launch_bounds__(256, 2) void fattn_kernel(
    const __half* __restrict__ Q, const __half* __restrict__ K,
    const __half* __restrict__ V, float* __restrict__ O)
{
    extern __shared__ char dsm[];     // NSTAGE * STAGE_B = 73728 B

    const int tid  = threadIdx.x;
    const int lane = tid & 31;
    const int warp = tid >> 5;
    const int h    = blockIdx.y;
    const int q0   = blockIdx.x * 128;
    const int hoff = h * DK;

    const unsigned smem_base = (unsigned)__cvta_generic_to_shared(dsm);

    // ---- group 1: Q tile into stage buffer 3 (first overwritten at t=1)
    {
        int qr = tid >> 1;
        int qc = (tid & 1) * 64;
        const char* src = (const char*)(Q + (size_t)(q0 + qr) * DM + hoff) + qc;
        unsigned dst = smem_base + 3 * STAGE_B + qr * QROWB + qc;
        cp16(dst, src);  cp16(dst + 16, src + 16);
        cp16(dst + 32, src + 32);  cp16(dst + 48, src + 48);
    }
    asm volatile("cp.async.commit_group;");

    // ---- K/V tile loader
    const int lrow = tid >> 2;
    const int lcb  = (tid & 3) * 32;
    const char* srcK = (const char*)(K + (size_t)lrow * DM + hoff) + lcb;
    const char* srcV = (const char*)(V + (size_t)lrow * DM + hoff) + lcb;
    const unsigned drow = smem_base + lrow * (KST * 2) + lcb;

    auto load_stage = [&](int t, int sbuf) {
        size_t goff = (size_t)t * 64 * DM * 2;
        unsigned d = drow + sbuf * STAGE_B;
        cp16(d, srcK + goff);           cp16(d + 16, srcK + goff + 16);
        cp16(d + TILE_B, srcV + goff);  cp16(d + TILE_B + 16, srcV + goff + 16);
    };

    load_stage(0, 0);
    asm volatile("cp.async.commit_group;");   // group 2
    load_stage(1, 1);
    asm volatile("cp.async.commit_group;");   // group 3

    // ---- lift Q fragments (wait for group 1 only; stages stay in flight)
    asm volatile("cp.async.wait_group 2;");
    __syncthreads();
    unsigned qf[4][4];
    {
        const unsigned qrow = warp * 16 + (lane & 15);
        #pragma unroll
        for (int s4 = 0; s4 < 4; s4++) {
            unsigned addr = smem_base + 3 * STAGE_B + qrow * QROWB
                            + (s4 * 16 + 8 * (lane >> 4)) * 2;
            ldsm_x4(qf[s4][0], qf[s4][1], qf[s4][2], qf[s4][3], addr);
        }
    }
    __syncthreads();

    const unsigned k_off = ((8 * ((lane >> 4) & 1) + (lane & 7)) * KST
                            + 8 * ((lane >> 3) & 1)) * 2;
    const unsigned v_off = ((8 * ((lane >> 3) & 1) + (lane & 7)) * KST
                            + 8 * (lane >> 4)) * 2;

    float o[8][4];
    #pragma unroll
    for (int df = 0; df < 8; df++)
        #pragma unroll
        for (int i = 0; i < 4; i++) o[df][i] = 0.0f;
    float m0 = -1e30f, m1 = -1e30f, l0s = 0.0f, l1s = 0.0f;
    float a0p = 1.0f, a1p = 1.0f;
    unsigned pp[8][2];

    const int NTILE = SEQ / 64;
    for (int t = 0; t < NTILE; t++) {
        asm volatile("cp.async.wait_group 1;");
        __syncthreads();
        if (t + 2 < NTILE) load_stage(t + 2, (t + 2) & 3);
        asm volatile("cp.async.commit_group;");

        // ---- QK(t)
        const unsigned stage = smem_base + (t & 3) * STAGE_B;
        float s[8][4];
        #pragma unroll
        for (int nf = 0; nf < 8; nf++)
            #pragma unroll
            for (int i = 0; i < 4; i++) s[nf][i] = 0.0f;

        #pragma unroll
        for (int s4 = 0; s4 < 4; s4++) {
            const int d0 = 16 * s4;
            #pragma unroll
            for (int nfp = 0; nfp < 4; nfp++) {
                const unsigned off = (unsigned)((16 * nfp) * KST + d0) * 2 + k_off;
                unsigned h0, h1, h2, h3;
                ldsm_x4(h0, h1, h2, h3, stage + off);
                mma_f16(s[2 * nfp],     qf[s4], h0, h1);
                mma_f16(s[2 * nfp + 1], qf[s4], h2, h3);
            }
        }

        // ---- PV(t-1): tensor work that softmax(t) will overlap
        if (t > 0) {
            const unsigned pstage = smem_base + ((t - 1) & 3) * STAGE_B;
            #pragma unroll
            for (int df = 0; df < 8; df++) {
                o[df][0] *= a0p; o[df][1] *= a0p;
                o[df][2] *= a1p; o[df][3] *= a1p;
            }
            #pragma unroll
            for (int kf2 = 0; kf2 < 4; kf2++) {
                unsigned af[4];
                af[0] = pp[2 * kf2][0];
                af[1] = pp[2 * kf2][1];
                af[2] = pp[2 * kf2 + 1][0];
                af[3] = pp[2 * kf2 + 1][1];
                #pragma unroll
                for (int dfp = 0; dfp < 4; dfp++) {
                    const unsigned off = (unsigned)((16 * kf2) * KST + 16 * dfp) * 2 + v_off;
                    unsigned b0, b1, b2, b3;
                    ldsm_x4_t(b0, b1, b2, b3, pstage + TILE_B + off);
                    mma_f16(o[2 * dfp],     af, b0, b1);
                    mma_f16(o[2 * dfp + 1], af, b2, b3);
                }
            }
        }

        // ---- softmax(t): produces pp / a for next iteration's PV
        float mx0 = -1e30f, mx1 = -1e30f;
        #pragma unroll
        for (int nf = 0; nf < 8; nf++) {
            mx0 = fmaxf(mx0, fmaxf(s[nf][0], s[nf][1]));
            mx1 = fmaxf(mx1, fmaxf(s[nf][2], s[nf][3]));
        }
        mx0 = fmaxf(mx0, __shfl_xor_sync(0xffffffffu, mx0, 1));
        mx0 = fmaxf(mx0, __shfl_xor_sync(0xffffffffu, mx0, 2));
        mx1 = fmaxf(mx1, __shfl_xor_sync(0xffffffffu, mx1, 1));
        mx1 = fmaxf(mx1, __shfl_xor_sync(0xffffffffu, mx1, 2));

        float nm0 = fmaxf(m0, mx0), nm1 = fmaxf(m1, mx1);
        a0p = ex2(m0 - nm0);
        a1p = ex2(m1 - nm1);
        m0 = nm0; m1 = nm1;

        float ps0 = 0.0f, ps1 = 0.0f;
        #pragma unroll
        for (int nf = 0; nf < 8; nf++) {
            float p0 = ex2(s[nf][0] - nm0);
            float p1 = ex2(s[nf][1] - nm0);
            float p2 = ex2(s[nf][2] - nm1);
            float p3 = ex2(s[nf][3] - nm1);
            ps0 += p0 + p1;
            ps1 += p2 + p3;
            pp[nf][0] = pack_f16(p0, p1);
            pp[nf][1] = pack_f16(p2, p3);
        }
        l0s = l0s * a0p + ps0;
        l1s = l1s * a1p + ps1;
    }

    // ---- tail: PV(NTILE-1)
    {
        const unsigned pstage = smem_base + ((NTILE - 1) & 3) * STAGE_B;
        #pragma unroll
        for (int df = 0; df < 8; df++) {
            o[df][0] *= a0p; o[df][1] *= a0p;
            o[df][2] *= a1p; o[df][3] *= a1p;
        }
        #pragma unroll
        for (int kf2 = 0; kf2 < 4; kf2++) {
            unsigned af[4];
            af[0] = pp[2 * kf2][0];
            af[1] = pp[2 * kf2][1];
            af[2] = pp[2 * kf2 + 1][0];
            af[3] = pp[2 * kf2 + 1][1];
            #pragma unroll
            for (int dfp = 0; dfp < 4; dfp++) {
                const unsigned off = (unsigned)((16 * kf2) * KST + 16 * dfp) * 2 + v_off;
                unsigned b0, b1, b2, b3;
                ldsm_x4_t(b0, b1, b2, b3, pstage + TILE_B + off);
                mma_f16(o[2 * dfp],     af, b0, b1);
                mma_f16(o[2 * dfp + 1], af, b2, b3);
            }
        }
    }

    l0s += __shfl_xor_sync(0xffffffffu, l0s, 1);
    l0s += __shfl_xor_sync(0xffffffffu, l0s, 2);
    l1s += __shfl_xor_sync(0xffffffffu, l1s, 1);
    l1s += __shfl_xor_sync(0xffffffffu, l1s, 2);
    float i0 = 1.0f / l0s, i1 = 1.0f / l1s;

    const int grow = q0 + warp * 16 + (lane >> 2);
    #pragma unroll
    for (int df = 0; df < 8; df++) {
        int col = hoff + df * 8 + 2 * (lane & 3);
        *(float2*)(O + (size_t)grow * DM + col) =
            make_float2(o[df][0] * i0, o[df][1] * i0);
        *(float2*)(O + (size_t)(grow + 8) * DM + col) =
            make_float2(o[df][2] * i1, o[df][3] * i1);
    }
}

// ---------------------------------------------------------------------------
extern "C" void kernel_launch(void* const* d_in, const int* in_sizes, int n_in,
                              void* d_out, int out_size)
{
    const float* query = (const float*)d_in[0];
    const float* key   = (const float*)d_in[1];
    const float* value = (const float*)d_in[2];
    const float* W_q   = (const float*)d_in[3];
    const float* b_q   = (const float*)d_in[4];
    const float* W_k   = (const float*)d_in[5];
    const float* b_k   = (const float*)d_in[6];
    const float* W_v   = (const float*)d_in[7];
    const float* b_v   = (const float*)d_in[8];
    const float* W_o   = (const float*)d_in[9];
    const float* b_o   = (const float*)d_in[10];
    float* out = (float*)d_out;

    __half *qi, *ki, *vi, *wq, *wk, *wv, *Qp, *Kp, *Vp;
    float *Ap;
    cudaGetSymbolAddress((void**)&qi, g_qi);
    cudaGetSymbolAddress((void**)&ki, g_ki);
    cudaGetSymbolAddress((void**)&vi, g_vi);
    cudaGetSymbolAddress((void**)&wq, g_wq);
    cudaGetSymbolAddress((void**)&wk, g_wk);
    cudaGetSymbolAddress((void**)&wv, g_wv);
    cudaGetSymbolAddress((void**)&Qp, g_Qs);
    cudaGetSymbolAddress((void**)&Kp, g_K);
    cudaGetSymbolAddress((void**)&Vp, g_V);
    cudaGetSymbolAddress((void**)&Ap, g_attn);

    const float SC = 0.125f * 1.4426950408889634f;   // 1/sqrt(64) * log2(e)

    const int gsmem = 2 * GBUF_B;                    // 81920 B
    const int psmem = FNST * FSTG_B;                 // 61440 B
    const int fsmem = NSTAGE * STAGE_B;              // 73728 B
    static int attr_set = 0;
    if (!attr_set) {
        cudaFuncSetAttribute(gemm_split, cudaFuncAttributeMaxDynamicSharedMemorySize, gsmem);
        cudaFuncSetAttribute(gemm_f16a, cudaFuncAttributeMaxDynamicSharedMemorySize, psmem);
        cudaFuncSetAttribute(fattn_kernel, cudaFuncAttributeMaxDynamicSharedMemorySize, fsmem);
        attr_set = 1;
    }

    // fp32 -> fp16 pre-conversion (inputs + weights)
    cvt3_kernel<<<dim3(SEQ * DM / 1024, 3), 256>>>(query, key, value, qi, ki, vi);
    cvt3_kernel<<<dim3(DM * DM / 1024, 3), 256>>>(W_q, W_k, W_v, wq, wk, wv);

    dim3 ggrd(DM / 128, SEQ / 128);
    gemm_f16a<<<ggrd, 256, psmem>>>(qi, wq, b_q, Qp, SC,   SEQ, DM, DM);
    gemm_f16a<<<ggrd, 256, psmem>>>(ki, wk, b_k, Kp, 1.0f, SEQ, DM, DM);
    gemm_f16a<<<ggrd, 256, psmem>>>(vi, wv, b_v, Vp, 1.0f, SEQ, DM, DM);

    dim3 agrd(SEQ / 128, NH);
    fattn_kernel<<<agrd, 256, fsmem>>>(Qp, Kp, Vp, Ap);

    gemm_split<<<ggrd, 256, gsmem>>>(Ap, W_o, b_o, out, SEQ, DM, DM);
}